// round 14
// baseline (speedup 1.0000x reference)
#include <cuda_runtime.h>
#include <cuda_bf16.h>
#include <cstdint>

#define NN 100000
#define NE 1600000
#define C_IN 128
#define HIDC 256
#define C_OUT 32
#define BN_EPS 1e-5f
#define SLOPE 0.1f
#define NBW 12500   // node-blocks per tile pass (8 warps/block * 12500 = 100000)

// ---------------- mma.sync helpers (sm_80+ baseline PTX, works on plain sm_103) ----------------
#define LDSM4(r, addr) \
    asm volatile("ldmatrix.sync.aligned.m8n8.x4.shared.b16 {%0,%1,%2,%3}, [%4];" \
        : "=r"((r)[0]), "=r"((r)[1]), "=r"((r)[2]), "=r"((r)[3]) : "r"(addr))

#define MMA_BF16(d, a, b) \
    asm volatile("mma.sync.aligned.m16n8k16.row.col.f32.bf16.bf16.f32 " \
        "{%0,%1,%2,%3}, {%4,%5,%6,%7}, {%8,%9}, {%0,%1,%2,%3};" \
        : "+f"((d)[0]), "+f"((d)[1]), "+f"((d)[2]), "+f"((d)[3]) \
        : "r"((a)[0]), "r"((a)[1]), "r"((a)[2]), "r"((a)[3]), "r"((b)[0]), "r"((b)[1]))

__device__ __forceinline__ uint32_t smem_u32(const void* p) {
    uint32_t a;
    asm("{ .reg .u64 t; cvta.to.shared.u64 t, %1; cvt.u32.u64 %0, t; }" : "=r"(a) : "l"(p));
    return a;
}

__device__ __forceinline__ unsigned short bf_hi(float x) {
    __nv_bfloat16 h = __float2bfloat16(x);
    return *reinterpret_cast<unsigned short*>(&h);
}
__device__ __forceinline__ float bf_back(unsigned short u) {
    __nv_bfloat16 h = *reinterpret_cast<__nv_bfloat16*>(&u);
    return __bfloat162float(h);
}

// ---------------- scratch ----------------
__device__ float g_deg[NN];
__device__ float g_dinv[NN];
__device__ int   g_cnt[NN];
__device__ int   g_cur[NN];
__device__ int   g_rowptr[NN + 1];
__device__ int   g_bsum[256];
__device__ int   g_boff[256];
__device__ int   g_col[NE];
__device__ float g_val[NE];
__device__ float g_bufC[(size_t)NN * HIDC];
__device__ __nv_bfloat16 g_Ahi[(size_t)NN * HIDC];
__device__ __nv_bfloat16 g_Alo[(size_t)NN * HIDC];
__device__ __nv_bfloat16 g_A2hi[(size_t)NN * HIDC];
__device__ __nv_bfloat16 g_A2lo[(size_t)NN * HIDC];
// transposed bf16 split weights, packed: W1t(32768) W2t(65536) W3t(65536) Wl1t(65536) Wl2t(8192)
__device__ __nv_bfloat16 g_Whi[237568];
__device__ __nv_bfloat16 g_Wlo[237568];
__device__ float g_sum[HIDC];
__device__ float g_sumsq[HIDC];
__device__ float g_scale[HIDC];
__device__ float g_shift[HIDC];

// ---------------- preprocessing ----------------
__global__ void k_init() {
    int i = blockIdx.x * blockDim.x + threadIdx.x;
    if (i < NN) { g_deg[i] = 0.f; g_cnt[i] = 0; g_cur[i] = 0; }
    if (i < HIDC) { g_sum[i] = 0.f; g_sumsq[i] = 0.f; }
}

__global__ void k_deg(const int* __restrict__ dst, const float* __restrict__ ew) {
    int e = blockIdx.x * blockDim.x + threadIdx.x;
    if (e < NE) {
        int d = dst[e];
        atomicAdd(&g_deg[d], ew[e]);
        atomicAdd(&g_cnt[d], 1);
    }
}

__global__ void k_dinv() {
    int i = blockIdx.x * blockDim.x + threadIdx.x;
    if (i < NN) g_dinv[i] = rsqrtf(g_deg[i] + 1.0f);  // +1 = self-loop
}

// two-level scan
#define SCB 512
#define NBLK ((NN + SCB - 1) / SCB)   // 196
__global__ void k_scan1() {
    __shared__ int sd[SCB];
    int tid = threadIdx.x;
    int i = blockIdx.x * SCB + tid;
    int v = (i < NN) ? g_cnt[i] : 0;
    sd[tid] = v;
    __syncthreads();
    #pragma unroll
    for (int d = 1; d < SCB; d <<= 1) {
        int t = (tid >= d) ? sd[tid - d] : 0;
        __syncthreads();
        sd[tid] += t;
        __syncthreads();
    }
    if (i < NN) g_rowptr[i] = sd[tid] - v;       // block-local exclusive
    if (tid == SCB - 1) g_bsum[blockIdx.x] = sd[tid];
}
__global__ void k_scan2() {
    __shared__ int sd[256];
    int tid = threadIdx.x;
    int v = (tid < NBLK) ? g_bsum[tid] : 0;
    sd[tid] = v;
    __syncthreads();
    #pragma unroll
    for (int d = 1; d < 256; d <<= 1) {
        int t = (tid >= d) ? sd[tid - d] : 0;
        __syncthreads();
        sd[tid] += t;
        __syncthreads();
    }
    if (tid < NBLK) g_boff[tid] = sd[tid] - v;   // exclusive block offsets
    if (tid == 0) g_rowptr[NN] = NE;
}
__global__ void k_scan3() {
    int i = blockIdx.x * blockDim.x + threadIdx.x;
    if (i < NN) g_rowptr[i] += g_boff[i / SCB];
}

__global__ void k_scatter(const int* __restrict__ src, const int* __restrict__ dst,
                          const float* __restrict__ ew) {
    int e = blockIdx.x * blockDim.x + threadIdx.x;
    if (e < NE) {
        int s = src[e];
        int d = dst[e];
        int p = atomicAdd(&g_cur[d], 1);
        int idx = g_rowptr[d] + p;
        g_col[idx] = s;
        g_val[idx] = g_dinv[s] * ew[e] * g_dinv[d];
    }
}

// ---------------- weight transpose + bf16 split: Wt[n][k] = W[k][n] ----------------
__global__ void k_wsplit(const float* __restrict__ W, __nv_bfloat16* __restrict__ Whi,
                         __nv_bfloat16* __restrict__ Wlo, int K, int N) {
    int idx = blockIdx.x * blockDim.x + threadIdx.x;
    if (idx >= K * N) return;
    int n = idx / K, k = idx % K;
    float v = W[(size_t)k * N + n];
    unsigned short h = bf_hi(v);
    float r = v - bf_back(h);
    Whi[idx] = *reinterpret_cast<__nv_bfloat16*>(&h);
    unsigned short l = bf_hi(r);
    Wlo[idx] = *reinterpret_cast<__nv_bfloat16*>(&l);
}

// ---------------- store helper: 4 floats -> hi/lo bf16 (2x uint2) ----------------
__device__ __forceinline__ void store_hl4(__nv_bfloat16* Ohi, __nv_bfloat16* Olo,
                                          size_t base, float a, float b, float c, float d) {
    unsigned short h0 = bf_hi(a), h1 = bf_hi(b), h2 = bf_hi(c), h3 = bf_hi(d);
    unsigned short l0 = bf_hi(a - bf_back(h0)), l1 = bf_hi(b - bf_back(h1)),
                   l2 = bf_hi(c - bf_back(h2)), l3 = bf_hi(d - bf_back(h3));
    uint2 H = make_uint2((uint32_t)h0 | ((uint32_t)h1 << 16), (uint32_t)h2 | ((uint32_t)h3 << 16));
    uint2 L = make_uint2((uint32_t)l0 | ((uint32_t)l1 << 16), (uint32_t)l2 | ((uint32_t)l3 << 16));
    *reinterpret_cast<uint2*>(Ohi + base) = H;
    *reinterpret_cast<uint2*>(Olo + base) = L;
}

__device__ __forceinline__ float4 bn4(float4 t, float4 sc, float4 sh) {
    float4 r;
    r.x = t.x * sc.x + sh.x; r.x = r.x >= 0.f ? r.x : SLOPE * r.x;
    r.y = t.y * sc.y + sh.y; r.y = r.y >= 0.f ? r.y : SLOPE * r.y;
    r.z = t.z * sc.z + sh.z; r.z = r.z >= 0.f ? r.z : SLOPE * r.z;
    r.w = t.w * sc.w + sh.w; r.w = r.w >= 0.f ? r.w : SLOPE * r.w;
    return r;
}

// ---------------- channel-tiled aggregation -> bf16 hi/lo ----------------
// 64 channels per pass; per-pass gathered table = NN*64*4B = 25.6MB (L2-resident).
// Grid ordered tile-major so passes execute roughly sequentially across waves.
// BNF: apply BN(scale,shift)+leaky to source features while gathering.
template <int F, bool BNF>
__global__ void k_agg_t(const float* __restrict__ feat,
                        __nv_bfloat16* __restrict__ Ohi, __nv_bfloat16* __restrict__ Olo) {
    int tile = blockIdx.x / NBW;
    int nb   = blockIdx.x % NBW;
    int warp = nb * 8 + (threadIdx.x >> 5);
    int lane = threadIdx.x & 31;
    int coff = tile * 64 + lane * 2;          // 2 channels per lane
    const int FH = F / 2;
    float2 sc, sh;
    if (BNF) {
        sc = *reinterpret_cast<const float2*>(&g_scale[coff]);
        sh = *reinterpret_cast<const float2*>(&g_shift[coff]);
    }
    float ds = g_dinv[warp];
    ds *= ds;
    const float2* base = reinterpret_cast<const float2*>(feat);
    size_t ci = coff >> 1;
    float2 t = base[(size_t)warp * FH + ci];
    if (BNF) {
        t.x = t.x * sc.x + sh.x; t.x = t.x >= 0.f ? t.x : SLOPE * t.x;
        t.y = t.y * sc.y + sh.y; t.y = t.y >= 0.f ? t.y : SLOPE * t.y;
    }
    float ax = ds * t.x, ay = ds * t.y;
    int beg = g_rowptr[warp], end = g_rowptr[warp + 1];
    int e = beg;
    for (; e + 1 < end; e += 2) {
        int s0 = g_col[e];     float w0 = g_val[e];
        int s1 = g_col[e + 1]; float w1 = g_val[e + 1];
        float2 t0 = __ldg(&base[(size_t)s0 * FH + ci]);
        float2 t1 = __ldg(&base[(size_t)s1 * FH + ci]);
        if (BNF) {
            t0.x = t0.x * sc.x + sh.x; t0.x = t0.x >= 0.f ? t0.x : SLOPE * t0.x;
            t0.y = t0.y * sc.y + sh.y; t0.y = t0.y >= 0.f ? t0.y : SLOPE * t0.y;
            t1.x = t1.x * sc.x + sh.x; t1.x = t1.x >= 0.f ? t1.x : SLOPE * t1.x;
            t1.y = t1.y * sc.y + sh.y; t1.y = t1.y >= 0.f ? t1.y : SLOPE * t1.y;
        }
        ax += w0 * t0.x + w1 * t1.x;
        ay += w0 * t0.y + w1 * t1.y;
    }
    if (e < end) {
        int s = g_col[e];
        float w = g_val[e];
        float2 t2 = __ldg(&base[(size_t)s * FH + ci]);
        if (BNF) {
            t2.x = t2.x * sc.x + sh.x; t2.x = t2.x >= 0.f ? t2.x : SLOPE * t2.x;
            t2.y = t2.y * sc.y + sh.y; t2.y = t2.y >= 0.f ? t2.y : SLOPE * t2.y;
        }
        ax += w * t2.x;
        ay += w * t2.y;
    }
    size_t ob = (size_t)warp * F + coff;
    unsigned short h0 = bf_hi(ax), h1 = bf_hi(ay);
    unsigned short l0 = bf_hi(ax - bf_back(h0)), l1 = bf_hi(ay - bf_back(h1));
    *reinterpret_cast<uint32_t*>(Ohi + ob) = (uint32_t)h0 | ((uint32_t)h1 << 16);
    *reinterpret_cast<uint32_t*>(Olo + ob) = (uint32_t)l0 | ((uint32_t)l1 << 16);
}

// ---------------- tensor-core bf16-split GEMM (mma.sync) ----------------
// C[M, NTOT] = (Ahi+Alo)[M, KTOT] @ (Bhi+Blo)^T,  B stored [NTOT][KTOT] K-major.
// 3-term: Ahi*Bhi + Ahi*Blo + Alo*Bhi, fp32 accum.
// Block tile 128 x BN. MODE 0: store fp32 (+BN stats if STATS). MODE 1: +bias, leaky, hi/lo bf16.
// MODE 2: +bias fp32.
template <int BN, int KTOT, int MODE, bool STATS>
__global__ __launch_bounds__(256) void k_mma(
    const __nv_bfloat16* __restrict__ Ahi, const __nv_bfloat16* __restrict__ Alo,
    const __nv_bfloat16* __restrict__ Bhi, const __nv_bfloat16* __restrict__ Blo,
    float* __restrict__ C, const float* __restrict__ bias,
    __nv_bfloat16* __restrict__ Ohi, __nv_bfloat16* __restrict__ Olo, int NTOT)
{
    constexpr int WARPS_N = (BN == 128) ? 4 : 1;
    constexpr int WARPS_M = 8 / WARPS_N;
    constexpr int WM = 128 / WARPS_M;       // 64 or 16
    constexpr int WN = BN / WARPS_N;        // 32
    constexpr int MT = WM / 16;             // 4 or 1
    constexpr int NT4 = WN / 8;             // 4
    constexpr int SA = 40;                  // padded row stride (elems)

    __shared__ __align__(16) __nv_bfloat16 sA[2][128 * SA];
    __shared__ __align__(16) __nv_bfloat16 sB[2][BN * SA];
    __shared__ float sBias[BN];

    int tid = threadIdx.x;
    int lane = tid & 31, wid = tid >> 5;
    int wm = wid / WARPS_N, wn = wid % WARPS_N;
    int row0 = blockIdx.x * 128;
    int col0 = blockIdx.y * BN;

    if (MODE != 0 && tid < BN) sBias[tid] = bias[col0 + tid];

    float acc[MT][NT4][4];
    #pragma unroll
    for (int mt = 0; mt < MT; mt++)
        #pragma unroll
        for (int nt = 0; nt < NT4; nt++)
            #pragma unroll
            for (int q = 0; q < 4; q++) acc[mt][nt][q] = 0.f;

    uint32_t sA0 = smem_u32(sA), sB0 = smem_u32(sB);

    for (int k0 = 0; k0 < KTOT; k0 += 32) {
        #pragma unroll
        for (int p = 0; p < 2; p++) {
            const __nv_bfloat16* Ap = p ? Alo : Ahi;
            #pragma unroll
            for (int i = 0; i < 2; i++) {
                int idx = tid + i * 256;            // 0..511
                int row = idx >> 2, cq = (idx & 3) * 8;
                int gr = row0 + row;
                uint4 v = make_uint4(0, 0, 0, 0);
                if (gr < NN)
                    v = *reinterpret_cast<const uint4*>(Ap + (size_t)gr * KTOT + k0 + cq);
                *reinterpret_cast<uint4*>(&sA[p][row * SA + cq]) = v;
            }
            const __nv_bfloat16* Bp = p ? Blo : Bhi;
            for (int idx = tid; idx < BN * 4; idx += 256) {
                int row = idx >> 2, cq = (idx & 3) * 8;
                uint4 v = *reinterpret_cast<const uint4*>(Bp + (size_t)(col0 + row) * KTOT + k0 + cq);
                *reinterpret_cast<uint4*>(&sB[p][row * SA + cq]) = v;
            }
        }
        __syncthreads();
        #pragma unroll
        for (int kk = 0; kk < 32; kk += 16) {
            uint32_t af[2][MT][4];
            uint32_t bfr[2][NT4][2];
            #pragma unroll
            for (int p = 0; p < 2; p++) {
                #pragma unroll
                for (int mt = 0; mt < MT; mt++) {
                    uint32_t addr = sA0 + (uint32_t)p * (128 * SA * 2) +
                        ((uint32_t)(wm * WM + mt * 16 + (lane & 15)) * SA + kk + (lane >> 4) * 8) * 2;
                    LDSM4(af[p][mt], addr);
                }
                #pragma unroll
                for (int np = 0; np < NT4 / 2; np++) {
                    uint32_t addr = sB0 + (uint32_t)p * (BN * SA * 2) +
                        ((uint32_t)(wn * WN + np * 16 + (lane & 7) + (lane >> 4) * 8) * SA
                         + kk + ((lane >> 3) & 1) * 8) * 2;
                    uint32_t r4[4];
                    LDSM4(r4, addr);
                    bfr[p][np * 2][0] = r4[0]; bfr[p][np * 2][1] = r4[1];
                    bfr[p][np * 2 + 1][0] = r4[2]; bfr[p][np * 2 + 1][1] = r4[3];
                }
            }
            #pragma unroll
            for (int mt = 0; mt < MT; mt++)
                #pragma unroll
                for (int nt = 0; nt < NT4; nt++) {
                    MMA_BF16(acc[mt][nt], af[0][mt], bfr[0][nt]);   // hi*hi
                    MMA_BF16(acc[mt][nt], af[0][mt], bfr[1][nt]);   // hi*lo
                    MMA_BF16(acc[mt][nt], af[1][mt], bfr[0][nt]);   // lo*hi
                }
        }
        __syncthreads();
    }

    // ---- epilogue (nt-outer so per-column stats reduce cleanly) ----
    #pragma unroll
    for (int nt = 0; nt < NT4; nt++) {
        int cl = wn * WN + nt * 8 + (lane & 3) * 2;   // col within block tile
        int c = col0 + cl;
        float s0 = 0.f, q0 = 0.f, s1 = 0.f, q1 = 0.f;
        #pragma unroll
        for (int mt = 0; mt < MT; mt++) {
            int r0 = row0 + wm * WM + mt * 16 + (lane >> 2);
            #pragma unroll
            for (int h = 0; h < 2; h++) {
                int r = r0 + h * 8;
                if (r >= NN) continue;
                float v0 = acc[mt][nt][h * 2], v1 = acc[mt][nt][h * 2 + 1];
                if (MODE != 0) { v0 += sBias[cl]; v1 += sBias[cl + 1]; }
                if (MODE == 1) {
                    v0 = v0 >= 0.f ? v0 : SLOPE * v0;
                    v1 = v1 >= 0.f ? v1 : SLOPE * v1;
                    unsigned short h0 = bf_hi(v0), h1 = bf_hi(v1);
                    unsigned short l0 = bf_hi(v0 - bf_back(h0)), l1 = bf_hi(v1 - bf_back(h1));
                    *reinterpret_cast<uint32_t*>(Ohi + (size_t)r * NTOT + c) =
                        (uint32_t)h0 | ((uint32_t)h1 << 16);
                    *reinterpret_cast<uint32_t*>(Olo + (size_t)r * NTOT + c) =
                        (uint32_t)l0 | ((uint32_t)l1 << 16);
                } else {
                    *reinterpret_cast<float2*>(C + (size_t)r * NTOT + c) = make_float2(v0, v1);
                }
                if (STATS) {
                    s0 += v0; q0 += v0 * v0;
                    s1 += v1; q1 += v1 * v1;
                }
            }
        }
        if (STATS) {
            // reduce over the 8 lanes sharing this column pair (xor 4/8/16 preserves lane&3)
            #pragma unroll
            for (int off = 4; off <= 16; off <<= 1) {
                s0 += __shfl_xor_sync(0xffffffffu, s0, off);
                q0 += __shfl_xor_sync(0xffffffffu, q0, off);
                s1 += __shfl_xor_sync(0xffffffffu, s1, off);
                q1 += __shfl_xor_sync(0xffffffffu, q1, off);
            }
            if (lane < 4) {
                atomicAdd(&g_sum[c], s0);
                atomicAdd(&g_sum[c + 1], s1);
                atomicAdd(&g_sumsq[c], q0);
                atomicAdd(&g_sumsq[c + 1], q1);
            }
        }
    }
}

// ---------------- BN finalize ----------------
__global__ void k_finalize(const float* __restrict__ gamma, const float* __restrict__ beta) {
    int c = threadIdx.x;
    float m = g_sum[c] * (1.0f / NN);
    float var = g_sumsq[c] * (1.0f / NN) - m * m;
    float rs = rsqrtf(var + BN_EPS);
    float sc = gamma[c] * rs;
    g_scale[c] = sc;
    g_shift[c] = beta[c] - m * sc;
    g_sum[c] = 0.f;
    g_sumsq[c] = 0.f;
}

__global__ void k_bnleaky_hl(const float* __restrict__ in,
                             __nv_bfloat16* __restrict__ Ohi, __nv_bfloat16* __restrict__ Olo) {
    int i = blockIdx.x * blockDim.x + threadIdx.x;
    if (i >= NN * 64) return;
    int c = (i & 63) << 2;
    float4 v = reinterpret_cast<const float4*>(in)[i];
    float4 s = *reinterpret_cast<const float4*>(&g_scale[c]);
    float4 b = *reinterpret_cast<const float4*>(&g_shift[c]);
    v = bn4(v, s, b);
    store_hl4(Ohi, Olo, (size_t)i * 4, v.x, v.y, v.z, v.w);
}

// ---------------- driver ----------------
extern "C" void kernel_launch(void* const* d_in, const int* in_sizes, int n_in,
                              void* d_out, int out_size) {
    (void)in_sizes; (void)n_in; (void)out_size;
    const float* x   = (const float*)d_in[0];
    const int*   ei  = (const int*)d_in[1];   // int32 (jax x64 disabled)
    const float* ew  = (const float*)d_in[2];
    const float* W1  = (const float*)d_in[3];
    const float* g1  = (const float*)d_in[5];
    const float* be1 = (const float*)d_in[6];
    const float* W2  = (const float*)d_in[7];
    const float* g2  = (const float*)d_in[9];
    const float* be2 = (const float*)d_in[10];
    const float* W3  = (const float*)d_in[11];
    const float* g3  = (const float*)d_in[13];
    const float* be3 = (const float*)d_in[14];
    const float* Wl1 = (const float*)d_in[15];
    const float* bl1 = (const float*)d_in[16];
    const float* Wl2 = (const float*)d_in[17];
    const float* bl2 = (const float*)d_in[18];
    float* out = (float*)d_out;
    const int* src = ei;
    const int* dst = ei + NE;

    float* bufC;
    __nv_bfloat16 *Ahi, *Alo, *A2hi, *A2lo, *Whi, *Wlo;
    cudaGetSymbolAddress((void**)&bufC, g_bufC);
    cudaGetSymbolAddress((void**)&Ahi, g_Ahi);
    cudaGetSymbolAddress((void**)&Alo, g_Alo);
    cudaGetSymbolAddress((void**)&A2hi, g_A2hi);
    cudaGetSymbolAddress((void**)&A2lo, g_A2lo);
    cudaGetSymbolAddress((void**)&Whi, g_Whi);
    cudaGetSymbolAddress((void**)&Wlo, g_Wlo);

    const int TPB = 256;
    const int gN  = (NN + TPB - 1) / TPB;
    const int gE  = (NE + TPB - 1) / TPB;
    const int gM  = (NN + 127) / 128;       // 782
    const int gEl = (NN * 64 + TPB - 1) / TPB;
    dim3 gBig(gM, 2);                       // 256 output cols in 2x 128-wide tiles
    dim3 gSmall(gM, 1);

    // weight transpose + split (tiny)
    k_wsplit<<<(32768 + 255) / 256, TPB>>>(W1,  Whi,          Wlo,          C_IN, HIDC);
    k_wsplit<<<(65536 + 255) / 256, TPB>>>(W2,  Whi + 32768,  Wlo + 32768,  HIDC, HIDC);
    k_wsplit<<<(65536 + 255) / 256, TPB>>>(W3,  Whi + 98304,  Wlo + 98304,  HIDC, HIDC);
    k_wsplit<<<(65536 + 255) / 256, TPB>>>(Wl1, Whi + 163840, Wlo + 163840, HIDC, HIDC);
    k_wsplit<<<(8192 + 255) / 256,  TPB>>>(Wl2, Whi + 229376, Wlo + 229376, HIDC, C_OUT);

    // graph preprocessing
    k_init<<<gN, TPB>>>();
    k_deg<<<gE, TPB>>>(dst, ew);
    k_dinv<<<gN, TPB>>>();
    k_scan1<<<NBLK, SCB>>>();
    k_scan2<<<1, 256>>>();
    k_scan3<<<gN, TPB>>>();
    k_scatter<<<gE, TPB>>>(src, dst, ew);

    // Layer 1: Agg(x) @ W1 (+fused BN stats); channel-tiled agg: 2 passes of 64ch
    k_agg_t<128, false><<<NBW * 2, TPB>>>(x, Ahi, Alo);
    k_mma<128, 128, 0, true><<<gBig, TPB>>>(Ahi, Alo, Whi, Wlo, bufC, nullptr, nullptr, nullptr, HIDC);
    k_finalize<<<1, HIDC>>>(g1, be1);

    // Layer 2: Agg(bn1(bufC)) @ W2 — BN+leaky fused into the tiled gather (4 passes)
    k_agg_t<256, true><<<NBW * 4, TPB>>>(bufC, Ahi, Alo);
    k_mma<128, 256, 0, true><<<gBig, TPB>>>(Ahi, Alo, Whi + 32768, Wlo + 32768, bufC, nullptr, nullptr, nullptr, HIDC);
    k_finalize<<<1, HIDC>>>(g2, be2);

    // Layer 3
    k_agg_t<256, true><<<NBW * 4, TPB>>>(bufC, Ahi, Alo);
    k_mma<128, 256, 0, true><<<gBig, TPB>>>(Ahi, Alo, Whi + 98304, Wlo + 98304, bufC, nullptr, nullptr, nullptr, HIDC);
    k_finalize<<<1, HIDC>>>(g3, be3);
    k_bnleaky_hl<<<gEl, TPB>>>(bufC, A2hi, A2lo);

    // MLP head
    k_mma<128, 256, 1, false><<<gBig, TPB>>>(A2hi, A2lo, Whi + 163840, Wlo + 163840,
                                             nullptr, bl1, Ahi, Alo, HIDC);   // leaky(.@Wl1+bl1) -> hi/lo
    k_mma<32, 256, 2, false><<<gSmall, TPB>>>(Ahi, Alo, Whi + 229376, Wlo + 229376,
                                              out, bl2, nullptr, nullptr, C_OUT);  // .@Wl2+bl2
}

// round 17
// speedup vs baseline: 1.3056x; 1.3056x over previous
#include <cuda_runtime.h>
#include <cuda_bf16.h>
#include <cstdint>

#define NN 100000
#define NE 1600000
#define C_IN 128
#define HIDC 256
#define C_OUT 32
#define BN_EPS 1e-5f
#define SLOPE 0.1f

// ---------------- mma.sync helpers (sm_80+ baseline PTX, works on plain sm_103) ----------------
#define LDSM4(r, addr) \
    asm volatile("ldmatrix.sync.aligned.m8n8.x4.shared.b16 {%0,%1,%2,%3}, [%4];" \
        : "=r"((r)[0]), "=r"((r)[1]), "=r"((r)[2]), "=r"((r)[3]) : "r"(addr))

#define MMA_BF16(d, a, b) \
    asm volatile("mma.sync.aligned.m16n8k16.row.col.f32.bf16.bf16.f32 " \
        "{%0,%1,%2,%3}, {%4,%5,%6,%7}, {%8,%9}, {%0,%1,%2,%3};" \
        : "+f"((d)[0]), "+f"((d)[1]), "+f"((d)[2]), "+f"((d)[3]) \
        : "r"((a)[0]), "r"((a)[1]), "r"((a)[2]), "r"((a)[3]), "r"((b)[0]), "r"((b)[1]))

#define CP_ASYNC16(dst, src, sz) \
    asm volatile("cp.async.ca.shared.global [%0], [%1], 16, %2;" \
        :: "r"(dst), "l"(src), "r"(sz))
#define CP_COMMIT() asm volatile("cp.async.commit_group;")
#define CP_WAIT1()  asm volatile("cp.async.wait_group 1;")
#define CP_WAIT0()  asm volatile("cp.async.wait_group 0;")

__device__ __forceinline__ uint32_t smem_u32(const void* p) {
    uint32_t a;
    asm("{ .reg .u64 t; cvta.to.shared.u64 t, %1; cvt.u32.u64 %0, t; }" : "=r"(a) : "l"(p));
    return a;
}

__device__ __forceinline__ unsigned short bf_hi(float x) {
    __nv_bfloat16 h = __float2bfloat16(x);
    return *reinterpret_cast<unsigned short*>(&h);
}
__device__ __forceinline__ float bf_back(unsigned short u) {
    __nv_bfloat16 h = *reinterpret_cast<__nv_bfloat16*>(&u);
    return __bfloat162float(h);
}

// ---------------- scratch ----------------
__device__ float g_deg[NN];
__device__ float g_dinv[NN];
__device__ int   g_cnt[NN];
__device__ int   g_cur[NN];
__device__ int   g_rowptr[NN + 1];
__device__ int   g_bsum[256];
__device__ int   g_boff[256];
__device__ int   g_col[NE];
__device__ float g_val[NE];
__device__ float g_bufC[(size_t)NN * HIDC];
__device__ __nv_bfloat16 g_Ahi[(size_t)NN * HIDC];
__device__ __nv_bfloat16 g_Alo[(size_t)NN * HIDC];
__device__ __nv_bfloat16 g_A2hi[(size_t)NN * HIDC];
__device__ __nv_bfloat16 g_A2lo[(size_t)NN * HIDC];
// transposed bf16 split weights, packed: W1t(32768) W2t(65536) W3t(65536) Wl1t(65536) Wl2t(8192)
__device__ __nv_bfloat16 g_Whi[237568];
__device__ __nv_bfloat16 g_Wlo[237568];
__device__ float g_sum[HIDC];
__device__ float g_sumsq[HIDC];
__device__ float g_scale[HIDC];
__device__ float g_shift[HIDC];

// ---------------- preprocessing ----------------
__global__ void k_init() {
    int i = blockIdx.x * blockDim.x + threadIdx.x;
    if (i < NN) { g_deg[i] = 0.f; g_cnt[i] = 0; g_cur[i] = 0; }
    if (i < HIDC) { g_sum[i] = 0.f; g_sumsq[i] = 0.f; }
}

__global__ void k_deg(const int* __restrict__ dst, const float* __restrict__ ew) {
    int e = blockIdx.x * blockDim.x + threadIdx.x;
    if (e < NE) {
        int d = dst[e];
        atomicAdd(&g_deg[d], ew[e]);
        atomicAdd(&g_cnt[d], 1);
    }
}

__global__ void k_dinv() {
    int i = blockIdx.x * blockDim.x + threadIdx.x;
    if (i < NN) g_dinv[i] = rsqrtf(g_deg[i] + 1.0f);  // +1 = self-loop
}

// two-level scan
#define SCB 512
#define NBLK ((NN + SCB - 1) / SCB)   // 196
__global__ void k_scan1() {
    __shared__ int sd[SCB];
    int tid = threadIdx.x;
    int i = blockIdx.x * SCB + tid;
    int v = (i < NN) ? g_cnt[i] : 0;
    sd[tid] = v;
    __syncthreads();
    #pragma unroll
    for (int d = 1; d < SCB; d <<= 1) {
        int t = (tid >= d) ? sd[tid - d] : 0;
        __syncthreads();
        sd[tid] += t;
        __syncthreads();
    }
    if (i < NN) g_rowptr[i] = sd[tid] - v;       // block-local exclusive
    if (tid == SCB - 1) g_bsum[blockIdx.x] = sd[tid];
}
__global__ void k_scan2() {
    __shared__ int sd[256];
    int tid = threadIdx.x;
    int v = (tid < NBLK) ? g_bsum[tid] : 0;
    sd[tid] = v;
    __syncthreads();
    #pragma unroll
    for (int d = 1; d < 256; d <<= 1) {
        int t = (tid >= d) ? sd[tid - d] : 0;
        __syncthreads();
        sd[tid] += t;
        __syncthreads();
    }
    if (tid < NBLK) g_boff[tid] = sd[tid] - v;   // exclusive block offsets
    if (tid == 0) g_rowptr[NN] = NE;
}
__global__ void k_scan3() {
    int i = blockIdx.x * blockDim.x + threadIdx.x;
    if (i < NN) g_rowptr[i] += g_boff[i / SCB];
}

__global__ void k_scatter(const int* __restrict__ src, const int* __restrict__ dst,
                          const float* __restrict__ ew) {
    int e = blockIdx.x * blockDim.x + threadIdx.x;
    if (e < NE) {
        int s = src[e];
        int d = dst[e];
        int p = atomicAdd(&g_cur[d], 1);
        int idx = g_rowptr[d] + p;
        g_col[idx] = s;
        g_val[idx] = g_dinv[s] * ew[e] * g_dinv[d];
    }
}

// ---------------- weight transpose + bf16 split: Wt[n][k] = W[k][n] ----------------
__global__ void k_wsplit(const float* __restrict__ W, __nv_bfloat16* __restrict__ Whi,
                         __nv_bfloat16* __restrict__ Wlo, int K, int N) {
    int idx = blockIdx.x * blockDim.x + threadIdx.x;
    if (idx >= K * N) return;
    int n = idx / K, k = idx % K;
    float v = W[(size_t)k * N + n];
    unsigned short h = bf_hi(v);
    float r = v - bf_back(h);
    Whi[idx] = *reinterpret_cast<__nv_bfloat16*>(&h);
    unsigned short l = bf_hi(r);
    Wlo[idx] = *reinterpret_cast<__nv_bfloat16*>(&l);
}

// ---------------- store helper: 4 floats -> hi/lo bf16 (2x uint2) ----------------
__device__ __forceinline__ void store_hl4(__nv_bfloat16* Ohi, __nv_bfloat16* Olo,
                                          size_t base, float a, float b, float c, float d) {
    unsigned short h0 = bf_hi(a), h1 = bf_hi(b), h2 = bf_hi(c), h3 = bf_hi(d);
    unsigned short l0 = bf_hi(a - bf_back(h0)), l1 = bf_hi(b - bf_back(h1)),
                   l2 = bf_hi(c - bf_back(h2)), l3 = bf_hi(d - bf_back(h3));
    uint2 H = make_uint2((uint32_t)h0 | ((uint32_t)h1 << 16), (uint32_t)h2 | ((uint32_t)h3 << 16));
    uint2 L = make_uint2((uint32_t)l0 | ((uint32_t)l1 << 16), (uint32_t)l2 | ((uint32_t)l3 << 16));
    *reinterpret_cast<uint2*>(Ohi + base) = H;
    *reinterpret_cast<uint2*>(Olo + base) = L;
}

__device__ __forceinline__ float4 bn4(float4 t, float4 sc, float4 sh) {
    float4 r;
    r.x = t.x * sc.x + sh.x; r.x = r.x >= 0.f ? r.x : SLOPE * r.x;
    r.y = t.y * sc.y + sh.y; r.y = r.y >= 0.f ? r.y : SLOPE * r.y;
    r.z = t.z * sc.z + sh.z; r.z = r.z >= 0.f ? r.z : SLOPE * r.z;
    r.w = t.w * sc.w + sh.w; r.w = r.w >= 0.f ? r.w : SLOPE * r.w;
    return r;
}

// ---------------- aggregation (raw input) -> bf16 hi/lo, edge loop unrolled x2 ----------------
template <int F>
__global__ void k_agg_hl(const float* __restrict__ feat,
                         __nv_bfloat16* __restrict__ Ohi, __nv_bfloat16* __restrict__ Olo) {
    int warp = (blockIdx.x * blockDim.x + threadIdx.x) >> 5;
    if (warp >= NN) return;
    int lane = threadIdx.x & 31;
    const int V = F / 128;
    float4 acc[V];
    float ds = g_dinv[warp];
    ds *= ds;
    const float4* frow = reinterpret_cast<const float4*>(feat) + (size_t)warp * (F / 4);
    #pragma unroll
    for (int v = 0; v < V; v++) {
        float4 t = frow[v * 32 + lane];
        acc[v].x = ds * t.x; acc[v].y = ds * t.y; acc[v].z = ds * t.z; acc[v].w = ds * t.w;
    }
    int beg = g_rowptr[warp], end = g_rowptr[warp + 1];
    int e = beg;
    for (; e + 1 < end; e += 2) {
        int s0 = g_col[e];     float w0 = g_val[e];
        int s1 = g_col[e + 1]; float w1 = g_val[e + 1];
        const float4* r0p = reinterpret_cast<const float4*>(feat) + (size_t)s0 * (F / 4);
        const float4* r1p = reinterpret_cast<const float4*>(feat) + (size_t)s1 * (F / 4);
        float4 t0[V], t1[V];
        #pragma unroll
        for (int v = 0; v < V; v++) {
            t0[v] = __ldg(&r0p[v * 32 + lane]);
            t1[v] = __ldg(&r1p[v * 32 + lane]);
        }
        #pragma unroll
        for (int v = 0; v < V; v++) {
            acc[v].x += w0 * t0[v].x + w1 * t1[v].x;
            acc[v].y += w0 * t0[v].y + w1 * t1[v].y;
            acc[v].z += w0 * t0[v].z + w1 * t1[v].z;
            acc[v].w += w0 * t0[v].w + w1 * t1[v].w;
        }
    }
    if (e < end) {
        int s = g_col[e];
        float w = g_val[e];
        const float4* srow = reinterpret_cast<const float4*>(feat) + (size_t)s * (F / 4);
        #pragma unroll
        for (int v = 0; v < V; v++) {
            float4 t = __ldg(&srow[v * 32 + lane]);
            acc[v].x += w * t.x; acc[v].y += w * t.y; acc[v].z += w * t.z; acc[v].w += w * t.w;
        }
    }
    #pragma unroll
    for (int v = 0; v < V; v++) {
        size_t base = (size_t)warp * F + (size_t)(v * 32 + lane) * 4;
        store_hl4(Ohi, Olo, base, acc[v].x, acc[v].y, acc[v].z, acc[v].w);
    }
}

// ---------------- aggregation with fused BN+leaky on sources, edge loop unrolled x2 ----------------
template <int F>
__global__ void k_agg_bn(const float* __restrict__ feat,
                         __nv_bfloat16* __restrict__ Ohi, __nv_bfloat16* __restrict__ Olo) {
    int warp = (blockIdx.x * blockDim.x + threadIdx.x) >> 5;
    if (warp >= NN) return;
    int lane = threadIdx.x & 31;
    const int V = F / 128;
    float4 sc[V], sh[V];
    #pragma unroll
    for (int v = 0; v < V; v++) {
        int c = (v * 32 + lane) * 4;
        sc[v] = *reinterpret_cast<const float4*>(&g_scale[c]);
        sh[v] = *reinterpret_cast<const float4*>(&g_shift[c]);
    }
    float4 acc[V];
    float ds = g_dinv[warp];
    ds *= ds;
    const float4* frow = reinterpret_cast<const float4*>(feat) + (size_t)warp * (F / 4);
    #pragma unroll
    for (int v = 0; v < V; v++) {
        float4 t = bn4(frow[v * 32 + lane], sc[v], sh[v]);
        acc[v].x = ds * t.x; acc[v].y = ds * t.y; acc[v].z = ds * t.z; acc[v].w = ds * t.w;
    }
    int beg = g_rowptr[warp], end = g_rowptr[warp + 1];
    int e = beg;
    for (; e + 1 < end; e += 2) {
        int s0 = g_col[e];     float w0 = g_val[e];
        int s1 = g_col[e + 1]; float w1 = g_val[e + 1];
        const float4* r0p = reinterpret_cast<const float4*>(feat) + (size_t)s0 * (F / 4);
        const float4* r1p = reinterpret_cast<const float4*>(feat) + (size_t)s1 * (F / 4);
        float4 t0[V], t1[V];
        #pragma unroll
        for (int v = 0; v < V; v++) {
            t0[v] = __ldg(&r0p[v * 32 + lane]);
            t1[v] = __ldg(&r1p[v * 32 + lane]);
        }
        #pragma unroll
        for (int v = 0; v < V; v++) {
            float4 a = bn4(t0[v], sc[v], sh[v]);
            float4 b = bn4(t1[v], sc[v], sh[v]);
            acc[v].x += w0 * a.x + w1 * b.x;
            acc[v].y += w0 * a.y + w1 * b.y;
            acc[v].z += w0 * a.z + w1 * b.z;
            acc[v].w += w0 * a.w + w1 * b.w;
        }
    }
    if (e < end) {
        int s = g_col[e];
        float w = g_val[e];
        const float4* srow = reinterpret_cast<const float4*>(feat) + (size_t)s * (F / 4);
        #pragma unroll
        for (int v = 0; v < V; v++) {
            float4 a = bn4(__ldg(&srow[v * 32 + lane]), sc[v], sh[v]);
            acc[v].x += w * a.x; acc[v].y += w * a.y; acc[v].z += w * a.z; acc[v].w += w * a.w;
        }
    }
    #pragma unroll
    for (int v = 0; v < V; v++) {
        size_t base = (size_t)warp * F + (size_t)(v * 32 + lane) * 4;
        store_hl4(Ohi, Olo, base, acc[v].x, acc[v].y, acc[v].z, acc[v].w);
    }
}

// ---------------- tensor-core bf16-split GEMM (mma.sync, 2-stage cp.async pipeline) ----------------
// C[M, NTOT] = (Ahi+Alo)[M, KTOT] @ (Bhi+Blo)^T,  B stored [NTOT][KTOT] K-major.
// 3-term: Ahi*Bhi + Ahi*Blo + Alo*Bhi, fp32 accum.
// Block tile 128 x BN. MODE 0: store fp32 (+BN stats if STATS). MODE 1: +bias, leaky, hi/lo bf16.
// MODE 2: +bias fp32.
template <int BN, int KTOT, int MODE, bool STATS>
__global__ __launch_bounds__(256) void k_mma(
    const __nv_bfloat16* __restrict__ Ahi, const __nv_bfloat16* __restrict__ Alo,
    const __nv_bfloat16* __restrict__ Bhi, const __nv_bfloat16* __restrict__ Blo,
    float* __restrict__ C, const float* __restrict__ bias,
    __nv_bfloat16* __restrict__ Ohi, __nv_bfloat16* __restrict__ Olo, int NTOT)
{
    constexpr int WARPS_N = (BN == 128) ? 4 : 1;
    constexpr int WARPS_M = 8 / WARPS_N;
    constexpr int WM = 128 / WARPS_M;       // 64 or 16
    constexpr int WN = BN / WARPS_N;        // 32
    constexpr int MT = WM / 16;             // 4 or 1
    constexpr int NT4 = WN / 8;             // 4
    constexpr int SA = 40;                  // padded row stride (elems)
    constexpr int A_STRIDE = 128 * SA * 2;  // bytes per (stage, p) A buffer
    constexpr int B_STRIDE = BN * SA * 2;
    constexpr int NCH = KTOT / 32;

    extern __shared__ char dsm[];
    float* sBias = reinterpret_cast<float*>(dsm);
    const uint32_t base = smem_u32(dsm);
    const uint32_t aBase = base + 512;
    const uint32_t bBase = aBase + 4 * A_STRIDE;

    int tid = threadIdx.x;
    int lane = tid & 31, wid = tid >> 5;
    int wm = wid / WARPS_N, wn = wid % WARPS_N;
    int row0 = blockIdx.x * 128;
    int col0 = blockIdx.y * BN;

    if (MODE != 0 && tid < BN) sBias[tid] = bias[col0 + tid];

    float acc[MT][NT4][4];
    #pragma unroll
    for (int mt = 0; mt < MT; mt++)
        #pragma unroll
        for (int nt = 0; nt < NT4; nt++)
            #pragma unroll
            for (int q = 0; q < 4; q++) acc[mt][nt][q] = 0.f;

    // issue one chunk's cp.async loads into stage st
    auto issue = [&](int c, int st) {
        int kc0 = c * 32;
        #pragma unroll
        for (int p = 0; p < 2; p++) {
            const __nv_bfloat16* Ap = p ? Alo : Ahi;
            #pragma unroll
            for (int i = 0; i < 2; i++) {
                int idx = tid + i * 256;            // 0..511
                int row = idx >> 2, cq = (idx & 3) * 8;
                int gr = row0 + row;
                uint32_t dst = aBase + (st * 2 + p) * A_STRIDE + (uint32_t)(row * SA + cq) * 2;
                const void* src = Ap + (size_t)gr * KTOT + kc0 + cq;
                int sz = (gr < NN) ? 16 : 0;
                CP_ASYNC16(dst, src, sz);
            }
            const __nv_bfloat16* Bp = p ? Blo : Bhi;
            for (int idx = tid; idx < BN * 4; idx += 256) {
                int row = idx >> 2, cq = (idx & 3) * 8;
                uint32_t dst = bBase + (st * 2 + p) * B_STRIDE + (uint32_t)(row * SA + cq) * 2;
                const void* src = Bp + (size_t)(col0 + row) * KTOT + kc0 + cq;
                CP_ASYNC16(dst, src, 16);
            }
        }
        CP_COMMIT();
    };

    issue(0, 0);
    for (int c = 0; c < NCH; c++) {
        int st = c & 1;
        if (c + 1 < NCH) { issue(c + 1, (c + 1) & 1); CP_WAIT1(); }
        else             { CP_WAIT0(); }
        __syncthreads();
        #pragma unroll
        for (int kk = 0; kk < 32; kk += 16) {
            uint32_t af[2][MT][4];
            uint32_t bfr[2][NT4][2];
            #pragma unroll
            for (int p = 0; p < 2; p++) {
                #pragma unroll
                for (int mt = 0; mt < MT; mt++) {
                    uint32_t addr = aBase + (st * 2 + p) * A_STRIDE +
                        ((uint32_t)(wm * WM + mt * 16 + (lane & 15)) * SA + kk + (lane >> 4) * 8) * 2;
                    LDSM4(af[p][mt], addr);
                }
                #pragma unroll
                for (int np = 0; np < NT4 / 2; np++) {
                    uint32_t addr = bBase + (st * 2 + p) * B_STRIDE +
                        ((uint32_t)(wn * WN + np * 16 + (lane & 7) + (lane >> 4) * 8) * SA
                         + kk + ((lane >> 3) & 1) * 8) * 2;
                    uint32_t r4[4];
                    LDSM4(r4, addr);
                    bfr[p][np * 2][0] = r4[0]; bfr[p][np * 2][1] = r4[1];
                    bfr[p][np * 2 + 1][0] = r4[2]; bfr[p][np * 2 + 1][1] = r4[3];
                }
            }
            #pragma unroll
            for (int mt = 0; mt < MT; mt++)
                #pragma unroll
                for (int nt = 0; nt < NT4; nt++) {
                    MMA_BF16(acc[mt][nt], af[0][mt], bfr[0][nt]);   // hi*hi
                    MMA_BF16(acc[mt][nt], af[0][mt], bfr[1][nt]);   // hi*lo
                    MMA_BF16(acc[mt][nt], af[1][mt], bfr[0][nt]);   // lo*hi
                }
        }
        __syncthreads();
    }

    // ---- epilogue (nt-outer so per-column stats reduce cleanly) ----
    #pragma unroll
    for (int nt = 0; nt < NT4; nt++) {
        int cl = wn * WN + nt * 8 + (lane & 3) * 2;   // col within block tile
        int c = col0 + cl;
        float s0 = 0.f, q0 = 0.f, s1 = 0.f, q1 = 0.f;
        #pragma unroll
        for (int mt = 0; mt < MT; mt++) {
            int r0 = row0 + wm * WM + mt * 16 + (lane >> 2);
            #pragma unroll
            for (int h = 0; h < 2; h++) {
                int r = r0 + h * 8;
                if (r >= NN) continue;
                float v0 = acc[mt][nt][h * 2], v1 = acc[mt][nt][h * 2 + 1];
                if (MODE != 0) { v0 += sBias[cl]; v1 += sBias[cl + 1]; }
                if (MODE == 1) {
                    v0 = v0 >= 0.f ? v0 : SLOPE * v0;
                    v1 = v1 >= 0.f ? v1 : SLOPE * v1;
                    unsigned short h0 = bf_hi(v0), h1 = bf_hi(v1);
                    unsigned short l0 = bf_hi(v0 - bf_back(h0)), l1 = bf_hi(v1 - bf_back(h1));
                    *reinterpret_cast<uint32_t*>(Ohi + (size_t)r * NTOT + c) =
                        (uint32_t)h0 | ((uint32_t)h1 << 16);
                    *reinterpret_cast<uint32_t*>(Olo + (size_t)r * NTOT + c) =
                        (uint32_t)l0 | ((uint32_t)l1 << 16);
                } else {
                    *reinterpret_cast<float2*>(C + (size_t)r * NTOT + c) = make_float2(v0, v1);
                }
                if (STATS) {
                    s0 += v0; q0 += v0 * v0;
                    s1 += v1; q1 += v1 * v1;
                }
            }
        }
        if (STATS) {
            // reduce over the 8 lanes sharing this column pair (xor 4/8/16 preserves lane&3)
            #pragma unroll
            for (int off = 4; off <= 16; off <<= 1) {
                s0 += __shfl_xor_sync(0xffffffffu, s0, off);
                q0 += __shfl_xor_sync(0xffffffffu, q0, off);
                s1 += __shfl_xor_sync(0xffffffffu, s1, off);
                q1 += __shfl_xor_sync(0xffffffffu, q1, off);
            }
            if (lane < 4) {
                atomicAdd(&g_sum[c], s0);
                atomicAdd(&g_sum[c + 1], s1);
                atomicAdd(&g_sumsq[c], q0);
                atomicAdd(&g_sumsq[c + 1], q1);
            }
        }
    }
}

// ---------------- BN finalize ----------------
__global__ void k_finalize(const float* __restrict__ gamma, const float* __restrict__ beta) {
    int c = threadIdx.x;
    float m = g_sum[c] * (1.0f / NN);
    float var = g_sumsq[c] * (1.0f / NN) - m * m;
    float rs = rsqrtf(var + BN_EPS);
    float sc = gamma[c] * rs;
    g_scale[c] = sc;
    g_shift[c] = beta[c] - m * sc;
    g_sum[c] = 0.f;
    g_sumsq[c] = 0.f;
}

__global__ void k_bnleaky_hl(const float* __restrict__ in,
                             __nv_bfloat16* __restrict__ Ohi, __nv_bfloat16* __restrict__ Olo) {
    int i = blockIdx.x * blockDim.x + threadIdx.x;
    if (i >= NN * 64) return;
    int c = (i & 63) << 2;
    float4 v = reinterpret_cast<const float4*>(in)[i];
    float4 s = *reinterpret_cast<const float4*>(&g_scale[c]);
    float4 b = *reinterpret_cast<const float4*>(&g_shift[c]);
    v = bn4(v, s, b);
    store_hl4(Ohi, Olo, (size_t)i * 4, v.x, v.y, v.z, v.w);
}

// ---------------- driver ----------------
extern "C" void kernel_launch(void* const* d_in, const int* in_sizes, int n_in,
                              void* d_out, int out_size) {
    (void)in_sizes; (void)n_in; (void)out_size;
    const float* x   = (const float*)d_in[0];
    const int*   ei  = (const int*)d_in[1];   // int32 (jax x64 disabled)
    const float* ew  = (const float*)d_in[2];
    const float* W1  = (const float*)d_in[3];
    const float* g1  = (const float*)d_in[5];
    const float* be1 = (const float*)d_in[6];
    const float* W2  = (const float*)d_in[7];
    const float* g2  = (const float*)d_in[9];
    const float* be2 = (const float*)d_in[10];
    const float* W3  = (const float*)d_in[11];
    const float* g3  = (const float*)d_in[13];
    const float* be3 = (const float*)d_in[14];
    const float* Wl1 = (const float*)d_in[15];
    const float* bl1 = (const float*)d_in[16];
    const float* Wl2 = (const float*)d_in[17];
    const float* bl2 = (const float*)d_in[18];
    float* out = (float*)d_out;
    const int* src = ei;
    const int* dst = ei + NE;

    float* bufC;
    __nv_bfloat16 *Ahi, *Alo, *A2hi, *A2lo, *Whi, *Wlo;
    cudaGetSymbolAddress((void**)&bufC, g_bufC);
    cudaGetSymbolAddress((void**)&Ahi, g_Ahi);
    cudaGetSymbolAddress((void**)&Alo, g_Alo);
    cudaGetSymbolAddress((void**)&A2hi, g_A2hi);
    cudaGetSymbolAddress((void**)&A2lo, g_A2lo);
    cudaGetSymbolAddress((void**)&Whi, g_Whi);
    cudaGetSymbolAddress((void**)&Wlo, g_Wlo);

    const int TPB = 256;
    const int gN  = (NN + TPB - 1) / TPB;
    const int gE  = (NE + TPB - 1) / TPB;
    const int gAg = NN / 8;
    const int gM  = (NN + 127) / 128;       // 782
    const int gEl = (NN * 64 + TPB - 1) / TPB;
    dim3 gBig(gM, 2);                       // 256 output cols in 2x 128-wide tiles
    dim3 gSmall(gM, 1);

    // dynamic smem: bias(512) + A 4x10240 + B 4x(BN*40*2)
    const int SM128 = 512 + 4 * (128 * 40 * 2) + 4 * (128 * 40 * 2);  // 82432
    const int SM32  = 512 + 4 * (128 * 40 * 2) + 4 * (32 * 40 * 2);   // 51712
    cudaFuncSetAttribute(k_mma<128, 128, 0, true>,  cudaFuncAttributeMaxDynamicSharedMemorySize, SM128);
    cudaFuncSetAttribute(k_mma<128, 256, 0, true>,  cudaFuncAttributeMaxDynamicSharedMemorySize, SM128);
    cudaFuncSetAttribute(k_mma<128, 256, 1, false>, cudaFuncAttributeMaxDynamicSharedMemorySize, SM128);
    cudaFuncSetAttribute(k_mma<32, 256, 2, false>,  cudaFuncAttributeMaxDynamicSharedMemorySize, SM32);

    // weight transpose + split (tiny)
    k_wsplit<<<(32768 + 255) / 256, TPB>>>(W1,  Whi,          Wlo,          C_IN, HIDC);
    k_wsplit<<<(65536 + 255) / 256, TPB>>>(W2,  Whi + 32768,  Wlo + 32768,  HIDC, HIDC);
    k_wsplit<<<(65536 + 255) / 256, TPB>>>(W3,  Whi + 98304,  Wlo + 98304,  HIDC, HIDC);
    k_wsplit<<<(65536 + 255) / 256, TPB>>>(Wl1, Whi + 163840, Wlo + 163840, HIDC, HIDC);
    k_wsplit<<<(8192 + 255) / 256,  TPB>>>(Wl2, Whi + 229376, Wlo + 229376, HIDC, C_OUT);

    // graph preprocessing
    k_init<<<gN, TPB>>>();
    k_deg<<<gE, TPB>>>(dst, ew);
    k_dinv<<<gN, TPB>>>();
    k_scan1<<<NBLK, SCB>>>();
    k_scan2<<<1, 256>>>();
    k_scan3<<<gN, TPB>>>();
    k_scatter<<<gE, TPB>>>(src, dst, ew);

    // Layer 1: Agg(x) @ W1 (+fused BN stats)
    k_agg_hl<128><<<gAg, TPB>>>(x, Ahi, Alo);
    k_mma<128, 128, 0, true><<<gBig, TPB, SM128>>>(Ahi, Alo, Whi, Wlo, bufC, nullptr, nullptr, nullptr, HIDC);
    k_finalize<<<1, HIDC>>>(g1, be1);

    // Layer 2: Agg(bn1(bufC)) @ W2   (BN+leaky fused into the gather)
    k_agg_bn<256><<<gAg, TPB>>>(bufC, Ahi, Alo);
    k_mma<128, 256, 0, true><<<gBig, TPB, SM128>>>(Ahi, Alo, Whi + 32768, Wlo + 32768, bufC, nullptr, nullptr, nullptr, HIDC);
    k_finalize<<<1, HIDC>>>(g2, be2);

    // Layer 3
    k_agg_bn<256><<<gAg, TPB>>>(bufC, Ahi, Alo);
    k_mma<128, 256, 0, true><<<gBig, TPB, SM128>>>(Ahi, Alo, Whi + 98304, Wlo + 98304, bufC, nullptr, nullptr, nullptr, HIDC);
    k_finalize<<<1, HIDC>>>(g3, be3);
    k_bnleaky_hl<<<gEl, TPB>>>(bufC, A2hi, A2lo);

    // MLP head
    k_mma<128, 256, 1, false><<<gBig, TPB, SM128>>>(A2hi, A2lo, Whi + 163840, Wlo + 163840,
                                                    nullptr, bl1, Ahi, Alo, HIDC);  // leaky -> hi/lo
    k_mma<32, 256, 2, false><<<gSmall, TPB, SM32>>>(Ahi, Alo, Whi + 229376, Wlo + 229376,
                                                    out, bl2, nullptr, nullptr, C_OUT);  // .@Wl2+bl2
}